// round 7
// baseline (speedup 1.0000x reference)
#include <cuda_runtime.h>
#include <cstdint>

#define NCLS   100
#define NCH    25           // 100/4 vec4 chunks
#define BATCH  4096
#define NITER  100
#define NT     256
#define NWARP  8
#define EPC    32           // elements per CTA (one per lane)
#define RPW    13           // padded rows per warp (8*13=104)
#define KROWS  104          // K padded with 4 zero rows

// smem float offsets
#define OFF_K   0
#define OFF_A   (KROWS*NCLS)            // 10400
#define OFF_B   (OFF_A + EPC*NCLS)      // +3200
#define OFF_MU  (OFF_B + EPC*NCLS)      // +3200
#define OFF_RED (OFF_MU + EPC*NCLS)     // 3*256 floats
#define OFF_TG  (OFF_RED + 768)         // 32 ints
#define SMEM_FLOATS (OFF_TG + 32)
#define SMEM_BYTES  (SMEM_FLOATS*4)     // 83328 B

__device__ float g_costs[BATCH];
__device__ int   g_is64;

// Probe target dtype (jax "int64" is often int32 in practice).
__global__ void detect_dtype_kernel(const int* __restrict__ t)
{
    if(threadIdx.x == 0 && blockIdx.x == 0){
        int is64 = 1;
        for(int k = 0; k < 64; k++){
            int lo = t[2*k], hi = t[2*k+1];
            if(hi != 0 || (unsigned)lo >= NCLS){ is64 = 0; break; }
        }
        g_is64 = is64;
    }
}

__device__ __forceinline__ float warp_sum(float v){
#pragma unroll
    for(int o=16;o>0;o>>=1) v += __shfl_xor_sync(0xffffffffu, v, o);
    return v;
}
__device__ __forceinline__ float warp_max(float v){
#pragma unroll
    for(int o=16;o>0;o>>=1) v = fmaxf(v, __shfl_xor_sync(0xffffffffu, v, o));
    return v;
}
__device__ __forceinline__ unsigned long long fma2(unsigned long long a,
                                                   unsigned long long b,
                                                   unsigned long long c){
    unsigned long long d;
    asm("fma.rn.f32x2 %0, %1, %2, %3;" : "=l"(d) : "l"(a), "l"(b), "l"(c));
    return d;
}
__device__ __forceinline__ float2 unpack2(unsigned long long p){
    float2 r;
    asm("mov.b64 {%0,%1}, %2;" : "=f"(r.x), "=f"(r.y) : "l"(p));
    return r;
}

// acc[r] = sum_j K[wrow+r, j] * vin[lane_elem, j]
// K rows broadcast across lanes; vin per-lane (stride 100 floats, conflict-free vec4).
__device__ __forceinline__ void matvec_rows(const float* __restrict__ Ksh,
                                            const float* __restrict__ vin,
                                            int wrow, int lane, float acc[RPW])
{
    unsigned long long a2[RPW];
#pragma unroll
    for(int r=0;r<RPW;r++) a2[r] = 0ULL;

    const ulonglong2* V  = reinterpret_cast<const ulonglong2*>(vin + lane*NCLS);
    const ulonglong2* K2 = reinterpret_cast<const ulonglong2*>(Ksh + wrow*NCLS);

#pragma unroll 1
    for(int jc=0;jc<NCH;jc++){
        ulonglong2 bq = V[jc];
#pragma unroll
        for(int r=0;r<RPW;r++){
            ulonglong2 kq = K2[r*NCH + jc];   // broadcast
            a2[r] = fma2(kq.x, bq.x, a2[r]);
            a2[r] = fma2(kq.y, bq.y, a2[r]);
        }
    }
#pragma unroll
    for(int r=0;r<RPW;r++){
        float2 p = unpack2(a2[r]);
        acc[r] = p.x + p.y;
    }
}

__global__ void __launch_bounds__(NT, 1)
sinkhorn_kernel(const float* __restrict__ pred, const void* __restrict__ target)
{
    extern __shared__ float smem[];
    float* Ksh   = smem + OFF_K;
    float* a_all = smem + OFF_A;
    float* b_all = smem + OFF_B;
    float* mu_sh = smem + OFF_MU;
    float* red   = smem + OFF_RED;
    int*   tg_sh = (int*)(smem + OFF_TG);

    const int tid  = threadIdx.x;
    const int lane = tid & 31;
    const int w    = tid >> 5;
    const int wrow = w * RPW;
    const int gbase = blockIdx.x * EPC;
    const int is64  = g_is64;

    // ---- build K = exp(-(i-j)^2 * 10/9801), pad rows 100..103 with zeros ----
    for(int idx = tid; idx < KROWS*NCLS; idx += NT){
        int i = idx / NCLS, j = idx - i*NCLS;
        float d = (float)(i - j);
        Ksh[idx] = (i < NCLS) ? __expf(d*d * (-10.0f/9801.0f)) : 0.f;
    }
    // b0 = 1
    for(int idx = tid; idx < EPC*NCLS; idx += NT) b_all[idx] = 1.0f;
    // targets
    if(tid < EPC){
        tg_sh[tid] = is64 ? (int)((const long long*)target)[gbase+tid]
                          : ((const int*)target)[gbase+tid];
    }

    // ---- softmax marginals (elem-major: warp w handles elems 4w..4w+3) ----
    {
        int  iS[4]; bool vld[4];
#pragma unroll
        for(int s=0;s<4;s++){ iS[s] = lane + 32*s; vld[s] = iS[s] < NCLS; }
#pragma unroll
        for(int e=0;e<4;e++){
            const int g = gbase + w*4 + e;
            float p[4];
#pragma unroll
            for(int s=0;s<4;s++) p[s] = vld[s] ? pred[g*NCLS + iS[s]] : -3.0e38f;
            float m = warp_max(fmaxf(fmaxf(p[0],p[1]), fmaxf(p[2],p[3])));
            float ex[4], ssum = 0.f;
#pragma unroll
            for(int s=0;s<4;s++){ ex[s] = vld[s] ? __expf(p[s]-m) : 0.f; ssum += ex[s]; }
            ssum = warp_sum(ssum);
            float inv = 1.f/ssum;
            float mu2[4]; float s2 = 0.f;
#pragma unroll
            for(int s=0;s<4;s++){ mu2[s] = vld[s] ? (ex[s]*inv + 1e-6f) : 0.f; s2 += mu2[s]; }
            s2 = warp_sum(s2);
            float inv2 = 1.f/s2;
#pragma unroll
            for(int s=0;s<4;s++)
                if(vld[s]) mu_sh[(w*4+e)*NCLS + iS[s]] = mu2[s]*inv2 + 1e-6f;
        }
    }
    __syncthreads();

    // ---- per-thread numerators for my (element=lane, rows wrow..wrow+12) ----
    const int tg = tg_sh[lane];
    const float NU_EFF0 = 1e-6f/1.0001f + 1e-6f;
    const float NU_EFF1 = (1.0f + 1e-6f)/1.0001f + 1e-6f;
    float mureg[RPW], nureg[RPW];
#pragma unroll
    for(int r=0;r<RPW;r++){
        int row = wrow + r;
        bool v = row < NCLS;
        mureg[r] = v ? mu_sh[lane*NCLS + row] : 0.f;
        nureg[r] = (v && row == tg) ? NU_EFF1 : NU_EFF0;
    }

    float acc[RPW];

    // ---- 200 half-iterations ----
#pragma unroll 1
    for(int h=0; h<2*NITER; h++){
        const bool astep = !(h & 1);
        const float* vin  = astep ? b_all : a_all;
        float*       vout = astep ? a_all : b_all;
        matvec_rows(Ksh, vin, wrow, lane, acc);
#pragma unroll
        for(int r=0;r<RPW;r++){
            int row = wrow + r;
            if(row < NCLS){
                float num = astep ? mureg[r] : nureg[r];
                vout[lane*NCLS + row] = __fdividef(num, acc[r]);
            }
        }
        __syncthreads();
    }

    // ================= epilogue (exact fp32) =================
    // kb = K * b_final
    matvec_rows(Ksh, b_all, wrow, lane, acc);
    float s0 = 0.f, s1 = 0.f, s2 = 0.f;
#pragma unroll
    for(int r=0;r<RPW;r++){
        int row = wrow + r;
        if(row < NCLS){
            float a      = a_all[lane*NCLS + row];
            float rowsum = fmaf(a, acc[r], 1e-4f);       // + NCLS*1e-6
            float mu     = mureg[r] - 1e-6f;
            float ri     = mu / rowsum;
            a_all[lane*NCLS + row] = a * ri;             // a2 overwrite
            float fi = (float)row - 49.5f;
            s0 += ri; s1 += ri*fi; s2 += ri*fi*fi;
        }
    }
    red[0*256 + w*32 + lane] = s0;
    red[1*256 + w*32 + lane] = s1;
    red[2*256 + w*32 + lane] = s2;
    __syncthreads();

    float S0 = 0.f, S1 = 0.f, S2 = 0.f;
#pragma unroll
    for(int ww=0; ww<NWARP; ww++){
        S0 += red[0*256 + ww*32 + lane];
        S1 += red[1*256 + ww*32 + lane];
        S2 += red[2*256 + ww*32 + lane];
    }

    const float NU0 = 1e-6f/1.0001f;
    const float NU1 = (1.0f + 1e-6f)/1.0001f;
    const float4* A4 = reinterpret_cast<const float4*>(a_all + lane*NCLS);

    // per output column j (= my rows), sum over i with exact fp32
    float cpart = 0.f;
#pragma unroll 1
    for(int r=0;r<RPW;r++){
        int j = wrow + r;
        if(j >= NCLS) break;
        const float4* K4 = reinterpret_cast<const float4*>(Ksh + j*NCLS);
        float A0 = 0.f, A1 = 0.f, A2 = 0.f;
#pragma unroll 5
        for(int ic=0;ic<NCH;ic++){
            float4 kq = K4[ic];                  // broadcast
            float4 aq = A4[ic];                  // per-lane a2
            float f0 = (float)(4*ic) - 49.5f;
            float t0 = kq.x*aq.x, t1 = kq.y*aq.y, t2 = kq.z*aq.z, t3 = kq.w*aq.w;
            A0 += (t0+t1)+(t2+t3);
            float u0 = t0*f0, u1 = t1*(f0+1.f), u2 = t2*(f0+2.f), u3 = t3*(f0+3.f);
            A1 += (u0+u1)+(u2+u3);
            A2 += fmaf(u0,f0, u1*(f0+1.f)) + fmaf(u2,(f0+2.f), u3*(f0+3.f));
        }
        // note: A2 term above must use u2*(f0+2): rewrite explicitly to be safe
        float bj = b_all[lane*NCLS + j];
        float fj = (float)j - 49.5f;
        float colsum = fmaf(bj, A0, 1e-6f*S0);
        float q  = A2 - 2.f*fj*A1 + fj*fj*A0;
        float qs = S2 - 2.f*fj*S1 + fj*fj*S0;
        float colC = fmaf(bj, q, 1e-6f*qs) * (1.0f/9801.0f);
        float nuj = (j == tg) ? NU1 : NU0;
        cpart += nuj * colC / colsum;
    }
    red[w*32 + lane] = cpart;
    __syncthreads();
    if(w == 0){
        float c = 0.f;
#pragma unroll
        for(int ww=0; ww<NWARP; ww++) c += red[ww*32 + lane];
        g_costs[gbase + lane] = c;
    }
}

__global__ void reduce_kernel(float* __restrict__ out)
{
    __shared__ float sh[1024];
    const int t = threadIdx.x;
    sh[t] = g_costs[t] + g_costs[t+1024] + g_costs[t+2048] + g_costs[t+3072];
    __syncthreads();
#pragma unroll
    for(int s=512;s>0;s>>=1){
        if(t<s) sh[t] += sh[t+s];
        __syncthreads();
    }
    if(t==0) out[0] = sh[0] * (1.0f/(float)BATCH);
}

extern "C" void kernel_launch(void* const* d_in, const int* in_sizes, int n_in,
                              void* d_out, int out_size)
{
    (void)in_sizes; (void)n_in; (void)out_size;
    const float* pred = (const float*)d_in[0];
    const void*  tgt  = d_in[1];
    float*       out  = (float*)d_out;

    cudaFuncSetAttribute(sinkhorn_kernel,
                         cudaFuncAttributeMaxDynamicSharedMemorySize, SMEM_BYTES);

    detect_dtype_kernel<<<1, 32>>>((const int*)tgt);
    sinkhorn_kernel<<<BATCH/EPC, NT, SMEM_BYTES>>>(pred, tgt);
    reduce_kernel<<<1, 1024>>>(out);
}